// round 1
// baseline (speedup 1.0000x reference)
#include <cuda_runtime.h>

// ---------------------------------------------------------------------------
// Problem constants
// ---------------------------------------------------------------------------
namespace {
constexpr int Bsz  = 4;
constexpr int Nseq = 4096;
constexpr int DIM  = 512;
constexpr int NH   = 8;
constexpr int DHd  = 64;
constexpr int ML   = 256;   // landmarks
constexpr int LBL  = 16;    // tokens per landmark block
constexpr int BH   = Bsz * NH;      // 32
constexpr int ROWS = Bsz * Nseq;    // 16384
constexpr int KCONV = 33;
constexpr int MM = ML * ML;         // 65536
}

// ---------------------------------------------------------------------------
// Scratch (static device arrays: allocation-free)
// ---------------------------------------------------------------------------
__device__ float g_xn   [ROWS * DIM];
__device__ float g_qkv  [ROWS * 3 * DIM];
__device__ float g_q    [BH * Nseq * DHd];
__device__ float g_k    [BH * Nseq * DHd];
__device__ float g_v    [BH * Nseq * DHd];
__device__ float g_ql   [BH * ML * DHd];
__device__ float g_kl   [BH * ML * DHd];
__device__ float g_a1   [BH * Nseq * ML];    // 134 MB
__device__ float g_a3   [BH * ML * Nseq];    // 134 MB
__device__ float g_a2   [BH * MM];
__device__ float g_z0   [BH * MM];
__device__ float g_z1   [BH * MM];
__device__ float g_xz   [BH * MM];
__device__ float g_w1   [BH * MM];
__device__ float g_w2   [BH * MM];
__device__ float g_a3v  [BH * ML * DHd];
__device__ float g_zv   [BH * ML * DHd];
__device__ float g_attn [BH * Nseq * DHd];
__device__ float g_attn_t[ROWS * DIM];
__device__ float g_red  [64];
__device__ float g_scal [1];

// ---------------------------------------------------------------------------
// LayerNorm (eps=1e-5): one block (128 thr) per row of 512
// ---------------------------------------------------------------------------
__global__ void layernorm_k(const float* __restrict__ x, const float* __restrict__ w,
                            const float* __restrict__ b, float* __restrict__ y)
{
    int row = blockIdx.x;
    int t = threadIdx.x;
    float4 v = reinterpret_cast<const float4*>(x + (size_t)row * DIM)[t];
    __shared__ float red[128];
    red[t] = v.x + v.y + v.z + v.w;
    __syncthreads();
    for (int o = 64; o > 0; o >>= 1) { if (t < o) red[t] += red[t + o]; __syncthreads(); }
    float mu = red[0] * (1.0f / DIM);
    __syncthreads();
    float dx = v.x - mu, dy = v.y - mu, dz = v.z - mu, dw = v.w - mu;
    red[t] = dx * dx + dy * dy + dz * dz + dw * dw;
    __syncthreads();
    for (int o = 64; o > 0; o >>= 1) { if (t < o) red[t] += red[t + o]; __syncthreads(); }
    float inv = rsqrtf(red[0] * (1.0f / DIM) + 1e-5f);
    float4 wv = reinterpret_cast<const float4*>(w)[t];
    float4 bv = reinterpret_cast<const float4*>(b)[t];
    float4 o4;
    o4.x = dx * inv * wv.x + bv.x;
    o4.y = dy * inv * wv.y + bv.y;
    o4.z = dz * inv * wv.z + bv.z;
    o4.w = dw * inv * wv.w + bv.w;
    reinterpret_cast<float4*>(y + (size_t)row * DIM)[t] = o4;
}

// ---------------------------------------------------------------------------
// Generic batched tiled SGEMM.
//   C = A(MxK, lda) * op(B), op(B)=B (KxN, ldb) if !TB, else B^T with B (NxK, ldb)
// Epilogues:
//   0: C = acc
//   1: C = alpha*I - acc
//   2: C = alpha*acc
//   3: C = acc,  C2 = alpha*I - acc
//   5: C = acc + bias[col] + resid[row*ldc+col]
// Requires: M%BM==0, N%BN==0, K%16==0, lda/ldb/ldc % 4 == 0.
// ---------------------------------------------------------------------------
template<int BM, int BN, int TM, int TN, bool TB, int EPI>
__global__ void __launch_bounds__(256)
gemm_k(const float* __restrict__ A, const float* __restrict__ Bm,
       float* __restrict__ C, float* __restrict__ C2,
       int M, int N, int K, int lda, int ldb, int ldc,
       long sA, long sB, long sC, float alpha,
       const float* __restrict__ bias, const float* __restrict__ resid)
{
    constexpr int BK = 16;
    constexpr int THREADS = (BM / TM) * (BN / TN); // 256
    __shared__ float As[BK][BM + 4];
    __shared__ float Bs[BK][BN + 4];

    int batch = blockIdx.z;
    A  += (long)batch * sA;
    Bm += (long)batch * sB;
    C  += (long)batch * sC;
    if (EPI == 3) C2 += (long)batch * sC;

    int bm = blockIdx.y * BM;
    int bn = blockIdx.x * BN;
    int tid = threadIdx.x;
    int tx = tid % (BN / TN);
    int ty = tid / (BN / TN);

    float acc[TM][TN];
#pragma unroll
    for (int i = 0; i < TM; i++)
#pragma unroll
        for (int j = 0; j < TN; j++) acc[i][j] = 0.f;

    for (int k0 = 0; k0 < K; k0 += BK) {
        // A tile: BM x BK, float4 along K
        constexpr int A_LOADS = BM * BK / (THREADS * 4);
#pragma unroll
        for (int i = 0; i < A_LOADS; i++) {
            int e  = tid + i * THREADS;
            int m  = e / (BK / 4);
            int kk = (e % (BK / 4)) * 4;
            float4 f = *reinterpret_cast<const float4*>(&A[(long)(bm + m) * lda + k0 + kk]);
            As[kk + 0][m] = f.x; As[kk + 1][m] = f.y;
            As[kk + 2][m] = f.z; As[kk + 3][m] = f.w;
        }
        // B tile
        constexpr int B_LOADS = BN * BK / (THREADS * 4);
        if (TB) {
#pragma unroll
            for (int i = 0; i < B_LOADS; i++) {
                int e  = tid + i * THREADS;
                int n  = e / (BK / 4);
                int kk = (e % (BK / 4)) * 4;
                float4 f = *reinterpret_cast<const float4*>(&Bm[(long)(bn + n) * ldb + k0 + kk]);
                Bs[kk + 0][n] = f.x; Bs[kk + 1][n] = f.y;
                Bs[kk + 2][n] = f.z; Bs[kk + 3][n] = f.w;
            }
        } else {
#pragma unroll
            for (int i = 0; i < B_LOADS; i++) {
                int e  = tid + i * THREADS;
                int kk = e / (BN / 4);
                int n  = (e % (BN / 4)) * 4;
                float4 f = *reinterpret_cast<const float4*>(&Bm[(long)(k0 + kk) * ldb + bn + n]);
                *reinterpret_cast<float4*>(&Bs[kk][n]) = f;
            }
        }
        __syncthreads();

#pragma unroll
        for (int kk = 0; kk < BK; kk++) {
            float ar[TM], br[TN];
#pragma unroll
            for (int i = 0; i < TM; i += 4) {
                float4 f = *reinterpret_cast<const float4*>(&As[kk][ty * TM + i]);
                ar[i] = f.x; ar[i + 1] = f.y; ar[i + 2] = f.z; ar[i + 3] = f.w;
            }
#pragma unroll
            for (int j = 0; j < TN; j += 4) {
                float4 f = *reinterpret_cast<const float4*>(&Bs[kk][tx * TN + j]);
                br[j] = f.x; br[j + 1] = f.y; br[j + 2] = f.z; br[j + 3] = f.w;
            }
#pragma unroll
            for (int i = 0; i < TM; i++)
#pragma unroll
                for (int j = 0; j < TN; j++) acc[i][j] += ar[i] * br[j];
        }
        __syncthreads();
    }

#pragma unroll
    for (int i = 0; i < TM; i++) {
        int row = bm + ty * TM + i;
#pragma unroll
        for (int j = 0; j < TN; j++) {
            int col = bn + tx * TN + j;
            long o = (long)row * ldc + col;
            float val = acc[i][j];
            if (EPI == 0)       C[o] = val;
            else if (EPI == 1)  C[o] = (row == col ? alpha : 0.f) - val;
            else if (EPI == 2)  C[o] = alpha * val;
            else if (EPI == 3) { C[o] = val; C2[o] = (row == col ? alpha : 0.f) - val; }
            else if (EPI == 5)  C[o] = val + bias[col] + resid[o];
        }
    }
}

template<int BM, int BN, int TM, int TN, bool TB, int EPI>
static void gemm(const float* A, const float* Bm, float* C, float* C2,
                 int M, int N, int K, int lda, int ldb, int ldc,
                 long sA, long sB, long sC, int batch, float alpha = 0.f,
                 const float* bias = nullptr, const float* resid = nullptr)
{
    dim3 g(N / BN, M / BM, batch);
    gemm_k<BM, BN, TM, TN, TB, EPI><<<g, 256>>>(A, Bm, C, C2, M, N, K, lda, ldb, ldc,
                                                sA, sB, sC, alpha, bias, resid);
}

// ---------------------------------------------------------------------------
// Scatter qkv [16384,1536] -> q,k,v as [B,H,N,D]; q scaled by DH^-0.5 = 1/8
// ---------------------------------------------------------------------------
__global__ void scatter_qkv_k(const float* __restrict__ qkv,
                              float* __restrict__ q, float* __restrict__ k,
                              float* __restrict__ v)
{
    int idx = blockIdx.x * 256 + threadIdx.x;   // ROWS * 1536
    int row = idx / (3 * DIM);
    int col = idx % (3 * DIM);
    float val = qkv[idx];
    int which = col / DIM;
    int c = col % DIM;
    int h = c / DHd, d = c % DHd;
    int b = row / Nseq, n = row % Nseq;
    size_t o = ((((size_t)b * NH + h) * Nseq) + n) * DHd + d;
    if (which == 0)      q[o] = val * 0.125f;
    else if (which == 1) k[o] = val;
    else                 v[o] = val;
}

// ---------------------------------------------------------------------------
// Landmarks: mean over LBL=16 consecutive tokens. grid BH*ML, block DHd
// ---------------------------------------------------------------------------
__global__ void landmark_k(const float* __restrict__ src, float* __restrict__ dst)
{
    int bm = blockIdx.x;        // bh*ML + m ; start row = bm*LBL
    int d = threadIdx.x;
    const float* p = src + (size_t)bm * LBL * DHd + d;
    float s = 0.f;
#pragma unroll
    for (int i = 0; i < LBL; i++) s += p[(size_t)i * DHd];
    dst[(size_t)bm * DHd + d] = s * (1.0f / LBL);
}

// ---------------------------------------------------------------------------
// Row softmax (in-place), one block (256 thr) per row, row staged in smem.
// ---------------------------------------------------------------------------
__global__ void softmax_k(float* __restrict__ p, int cols)
{
    extern __shared__ float sh[];
    __shared__ float red[256];
    float* row = p + (size_t)blockIdx.x * cols;
    int t = threadIdx.x;
    float m = -1e30f;
    for (int j = t; j < cols; j += 256) { float v = row[j]; sh[j] = v; m = fmaxf(m, v); }
    red[t] = m; __syncthreads();
    for (int o = 128; o > 0; o >>= 1) { if (t < o) red[t] = fmaxf(red[t], red[t + o]); __syncthreads(); }
    m = red[0];
    __syncthreads();
    float sum = 0.f;
    for (int j = t; j < cols; j += 256) { float e = __expf(sh[j] - m); sh[j] = e; sum += e; }
    red[t] = sum; __syncthreads();
    for (int o = 128; o > 0; o >>= 1) { if (t < o) red[t] += red[t + o]; __syncthreads(); }
    float inv = 1.0f / red[0];
    for (int j = t; j < cols; j += 256) row[j] = sh[j] * inv;
}

// ---------------------------------------------------------------------------
// Newton-Schulz pinv init. NOTE: jnp.max(col), jnp.max(row) are GLOBAL maxima
// over the whole [B,H,M] arrays (single scalar across all batches).
// ---------------------------------------------------------------------------
__global__ void pinv_absmax_k(const float* __restrict__ a2, float* __restrict__ red)
{
    int bh = blockIdx.x;
    const float* X = a2 + (size_t)bh * MM;
    int t = threadIdx.x;                 // 256
    float cs = 0.f, rs = 0.f;
    for (int j = 0; j < ML; j++) {
        cs += fabsf(X[(size_t)t * ML + j]);   // row t, sum over last axis
        rs += fabsf(X[(size_t)j * ML + t]);   // col t, sum over -2 axis
    }
    __shared__ float rc[256], rr[256];
    rc[t] = cs; rr[t] = rs; __syncthreads();
    for (int o = 128; o > 0; o >>= 1) {
        if (t < o) { rc[t] = fmaxf(rc[t], rc[t + o]); rr[t] = fmaxf(rr[t], rr[t + o]); }
        __syncthreads();
    }
    if (t == 0) { red[bh] = rc[0]; red[32 + bh] = rr[0]; }
}

__global__ void pinv_scalar_k(const float* __restrict__ red, float* __restrict__ scal)
{
    int t = threadIdx.x;   // 32
    float c = red[t], r = red[32 + t];
    for (int o = 16; o > 0; o >>= 1) {
        c = fmaxf(c, __shfl_down_sync(0xffffffffu, c, o));
        r = fmaxf(r, __shfl_down_sync(0xffffffffu, r, o));
    }
    if (t == 0) scal[0] = 1.0f / (c * r);
}

__global__ void pinv_zinit_k(const float* __restrict__ a2, const float* __restrict__ scal,
                             float* __restrict__ z)
{
    int idx = blockIdx.x * 256 + threadIdx.x;   // BH*MM
    int bh = idx >> 16;
    int r  = (idx >> 8) & 255;
    int c  = idx & 255;
    z[idx] = a2[((size_t)bh << 16) + ((size_t)c << 8) + r] * scal[0];
}

// ---------------------------------------------------------------------------
// Depthwise conv over sequence dim (K=33, pad 16), added into attn.
// ---------------------------------------------------------------------------
__global__ void conv_add_k(const float* __restrict__ v, const float* __restrict__ rw,
                           float* __restrict__ attn)
{
    int idx = blockIdx.x * 256 + threadIdx.x;   // BH*Nseq*DHd
    int d  = idx % DHd;
    int n  = (idx / DHd) % Nseq;
    int bh = idx / (DHd * Nseq);
    int h  = bh % NH;
    const float* vb = v + (size_t)bh * Nseq * DHd + d;
    float s = 0.f;
#pragma unroll
    for (int t = 0; t < KCONV; t++) {
        int nn = n + t - KCONV / 2;
        if (nn >= 0 && nn < Nseq) s += vb[(size_t)nn * DHd] * rw[h * KCONV + t];
    }
    attn[idx] += s;
}

// ---------------------------------------------------------------------------
// attn [B,H,N,D] -> [B*N, H*D]
// ---------------------------------------------------------------------------
__global__ void transpose_attn_k(const float* __restrict__ attn, float* __restrict__ o)
{
    int idx = blockIdx.x * 256 + threadIdx.x;   // ROWS*DIM
    int col = idx % DIM;
    int row = idx / DIM;
    int b = row / Nseq, n = row % Nseq;
    int h = col / DHd, d = col % DHd;
    o[idx] = attn[((((size_t)b * NH + h) * Nseq) + n) * DHd + d];
}

// ---------------------------------------------------------------------------
// Launch
// ---------------------------------------------------------------------------
extern "C" void kernel_launch(void* const* d_in, const int* in_sizes, int n_in,
                              void* d_out, int out_size)
{
    const float* x      = (const float*)d_in[0];
    const float* norm_w = (const float*)d_in[1];
    const float* norm_b = (const float*)d_in[2];
    const float* w_qkv  = (const float*)d_in[3];
    const float* w_out  = (const float*)d_in[4];
    const float* b_out  = (const float*)d_in[5];
    const float* res_w  = (const float*)d_in[6];
    float* out = (float*)d_out;

    float *xn, *qkv, *q, *k, *v, *ql, *kl, *a1, *a3, *a2;
    float *z0, *z1, *xz, *w1, *w2, *a3v, *zv, *attn, *attn_t, *red, *scal;
    cudaGetSymbolAddress((void**)&xn, g_xn);
    cudaGetSymbolAddress((void**)&qkv, g_qkv);
    cudaGetSymbolAddress((void**)&q, g_q);
    cudaGetSymbolAddress((void**)&k, g_k);
    cudaGetSymbolAddress((void**)&v, g_v);
    cudaGetSymbolAddress((void**)&ql, g_ql);
    cudaGetSymbolAddress((void**)&kl, g_kl);
    cudaGetSymbolAddress((void**)&a1, g_a1);
    cudaGetSymbolAddress((void**)&a3, g_a3);
    cudaGetSymbolAddress((void**)&a2, g_a2);
    cudaGetSymbolAddress((void**)&z0, g_z0);
    cudaGetSymbolAddress((void**)&z1, g_z1);
    cudaGetSymbolAddress((void**)&xz, g_xz);
    cudaGetSymbolAddress((void**)&w1, g_w1);
    cudaGetSymbolAddress((void**)&w2, g_w2);
    cudaGetSymbolAddress((void**)&a3v, g_a3v);
    cudaGetSymbolAddress((void**)&zv, g_zv);
    cudaGetSymbolAddress((void**)&attn, g_attn);
    cudaGetSymbolAddress((void**)&attn_t, g_attn_t);
    cudaGetSymbolAddress((void**)&red, g_red);
    cudaGetSymbolAddress((void**)&scal, g_scal);

    // 1. LayerNorm
    layernorm_k<<<ROWS, 128>>>(x, norm_w, norm_b, xn);

    // 2. QKV projection: [16384,512] x [512,1536]
    gemm<128, 128, 8, 8, false, 0>(xn, w_qkv, qkv, nullptr,
                                   ROWS, 3 * DIM, DIM, DIM, 3 * DIM, 3 * DIM,
                                   0, 0, 0, 1);
    scatter_qkv_k<<<ROWS * 3 * DIM / 256, 256>>>(qkv, q, k, v);

    // 3. Landmarks
    landmark_k<<<BH * ML, DHd>>>(q, ql);
    landmark_k<<<BH * ML, DHd>>>(k, kl);

    // 4. Similarities (NT: C = A * B^T over head dim)
    gemm<128, 128, 8, 8, true, 0>(q, kl, a1, nullptr,
                                  Nseq, ML, DHd, DHd, DHd, ML,
                                  (long)Nseq * DHd, (long)ML * DHd, (long)Nseq * ML, BH);
    gemm<64, 64, 4, 4, true, 0>(ql, kl, a2, nullptr,
                                ML, ML, DHd, DHd, DHd, ML,
                                (long)ML * DHd, (long)ML * DHd, (long)MM, BH);
    gemm<128, 128, 8, 8, true, 0>(ql, k, a3, nullptr,
                                  ML, Nseq, DHd, DHd, DHd, Nseq,
                                  (long)ML * DHd, (long)Nseq * DHd, (long)ML * Nseq, BH);

    // 5. Softmaxes
    softmax_k<<<BH * Nseq, 256, ML * 4>>>(a1, ML);
    softmax_k<<<BH * ML, 256, ML * 4>>>(a2, ML);
    softmax_k<<<BH * ML, 256, Nseq * 4>>>(a3, Nseq);

    // 6. pinv init (global max across all batches!)
    pinv_absmax_k<<<BH, 256>>>(a2, red);
    pinv_scalar_k<<<1, 32>>>(red, scal);
    pinv_zinit_k<<<BH * MM / 256, 256>>>(a2, scal, z0);

    // 7. Newton-Schulz iterations: z = 0.25 z (13I - xz(15I - xz(7I - xz)))
    float* zc = z0;
    float* zn = z1;
    for (int it = 0; it < 6; it++) {
        // xz = a2 @ z ; w1 = 7I - xz
        gemm<64, 64, 4, 4, false, 3>(a2, zc, xz, w1,
                                     ML, ML, ML, ML, ML, ML,
                                     (long)MM, (long)MM, (long)MM, BH, 7.f);
        // w2 = 15I - xz @ w1
        gemm<64, 64, 4, 4, false, 1>(xz, w1, w2, nullptr,
                                     ML, ML, ML, ML, ML, ML,
                                     (long)MM, (long)MM, (long)MM, BH, 15.f);
        // w1 = 13I - xz @ w2
        gemm<64, 64, 4, 4, false, 1>(xz, w2, w1, nullptr,
                                     ML, ML, ML, ML, ML, ML,
                                     (long)MM, (long)MM, (long)MM, BH, 13.f);
        // zn = 0.25 * zc @ w1
        gemm<64, 64, 4, 4, false, 2>(zc, w1, zn, nullptr,
                                     ML, ML, ML, ML, ML, ML,
                                     (long)MM, (long)MM, (long)MM, BH, 0.25f);
        float* tmp = zc; zc = zn; zn = tmp;
    }

    // 8. a3v = a3 @ v   [256,4096] x [4096,64]
    gemm<64, 64, 4, 4, false, 0>(a3, v, a3v, nullptr,
                                 ML, DHd, Nseq, Nseq, DHd, DHd,
                                 (long)ML * Nseq, (long)Nseq * DHd, (long)ML * DHd, BH);
    // 9. zv = z @ a3v   (reassociated: (a1 z)(a3 v) == a1 (z (a3 v)))
    gemm<64, 64, 4, 4, false, 0>(zc, a3v, zv, nullptr,
                                 ML, DHd, ML, ML, DHd, DHd,
                                 (long)MM, (long)ML * DHd, (long)ML * DHd, BH);
    // 10. attn = a1 @ zv  [4096,256] x [256,64]
    gemm<64, 64, 4, 4, false, 0>(a1, zv, attn, nullptr,
                                 Nseq, DHd, ML, ML, DHd, DHd,
                                 (long)Nseq * ML, (long)ML * DHd, (long)Nseq * DHd, BH);

    // 11. residual depthwise conv of v added into attn
    conv_add_k<<<BH * Nseq * DHd / 256, 256>>>(v, res_w, attn);

    // 12. transpose to [B*N, H*D]
    transpose_attn_k<<<ROWS * DIM / 256, 256>>>(attn, attn_t);

    // 13. out proj + bias + input residual -> d_out
    gemm<128, 128, 8, 8, false, 5>(attn_t, w_out, out, nullptr,
                                   ROWS, DIM, DIM, DIM, DIM, DIM,
                                   0, 0, 0, 1, 0.f, b_out, x);
}

// round 2
// speedup vs baseline: 1.0049x; 1.0049x over previous
#include <cuda_runtime.h>

// ---------------------------------------------------------------------------
// Problem constants
// ---------------------------------------------------------------------------
namespace {
constexpr int Bsz  = 4;
constexpr int Nseq = 4096;
constexpr int DIM  = 512;
constexpr int NH   = 8;
constexpr int DHd  = 64;
constexpr int ML   = 256;   // landmarks
constexpr int LBL  = 16;    // tokens per landmark block
constexpr int BH   = Bsz * NH;      // 32
constexpr int ROWS = Bsz * Nseq;    // 16384
constexpr int KCONV = 33;
constexpr int MM = ML * ML;         // 65536
}

// ---------------------------------------------------------------------------
// Scratch (static device arrays: allocation-free)
// ---------------------------------------------------------------------------
__device__ float g_xn   [ROWS * DIM];
__device__ float g_qkv  [ROWS * 3 * DIM];
__device__ float g_q    [BH * Nseq * DHd];
__device__ float g_k    [BH * Nseq * DHd];
__device__ float g_v    [BH * Nseq * DHd];
__device__ float g_ql   [BH * ML * DHd];
__device__ float g_kl   [BH * ML * DHd];
__device__ float g_a1   [BH * Nseq * ML];    // 134 MB
__device__ float g_a3   [BH * ML * Nseq];    // 134 MB
__device__ float g_a2   [BH * MM];
__device__ float g_z0   [BH * MM];
__device__ float g_z1   [BH * MM];
__device__ float g_xz   [BH * MM];
__device__ float g_w1   [BH * MM];
__device__ float g_w2   [BH * MM];
__device__ float g_a3v  [BH * ML * DHd];
__device__ float g_zv   [BH * ML * DHd];
__device__ float g_attn [BH * Nseq * DHd];
__device__ float g_attn_t[ROWS * DIM];
__device__ float g_red  [64];
__device__ float g_scal [1];

// ---------------------------------------------------------------------------
// LayerNorm (eps=1e-5): one block (128 thr) per row of 512
// ---------------------------------------------------------------------------
__global__ void layernorm_k(const float* __restrict__ x, const float* __restrict__ w,
                            const float* __restrict__ b, float* __restrict__ y)
{
    int row = blockIdx.x;
    int t = threadIdx.x;
    float4 v = reinterpret_cast<const float4*>(x + (size_t)row * DIM)[t];
    __shared__ float red[128];
    red[t] = v.x + v.y + v.z + v.w;
    __syncthreads();
    for (int o = 64; o > 0; o >>= 1) { if (t < o) red[t] += red[t + o]; __syncthreads(); }
    float mu = red[0] * (1.0f / DIM);
    __syncthreads();
    float dx = v.x - mu, dy = v.y - mu, dz = v.z - mu, dw = v.w - mu;
    red[t] = dx * dx + dy * dy + dz * dz + dw * dw;
    __syncthreads();
    for (int o = 64; o > 0; o >>= 1) { if (t < o) red[t] += red[t + o]; __syncthreads(); }
    float inv = rsqrtf(red[0] * (1.0f / DIM) + 1e-5f);
    float4 wv = reinterpret_cast<const float4*>(w)[t];
    float4 bv = reinterpret_cast<const float4*>(b)[t];
    float4 o4;
    o4.x = dx * inv * wv.x + bv.x;
    o4.y = dy * inv * wv.y + bv.y;
    o4.z = dz * inv * wv.z + bv.z;
    o4.w = dw * inv * wv.w + bv.w;
    reinterpret_cast<float4*>(y + (size_t)row * DIM)[t] = o4;
}

// ---------------------------------------------------------------------------
// Generic batched tiled SGEMM.
//   C = A(MxK, lda) * op(B), op(B)=B (KxN, ldb) if !TB, else B^T with B (NxK, ldb)
// Epilogues:
//   0: C = acc
//   1: C = alpha*I - acc
//   2: C = alpha*acc
//   3: C = acc,  C2 = alpha*I - acc
//   5: C = acc + bias[col] + resid[row*ldc+col]
// Requires: M%BM==0, N%BN==0, K%16==0, lda/ldb/ldc % 4 == 0.
// ---------------------------------------------------------------------------
template<int BM, int BN, int TM, int TN, bool TB, int EPI>
__global__ void __launch_bounds__(256)
gemm_k(const float* __restrict__ A, const float* __restrict__ Bm,
       float* __restrict__ C, float* __restrict__ C2,
       int M, int N, int K, int lda, int ldb, int ldc,
       long sA, long sB, long sC, float alpha,
       const float* __restrict__ bias, const float* __restrict__ resid)
{
    constexpr int BK = 16;
    constexpr int THREADS = (BM / TM) * (BN / TN); // 256
    __shared__ float As[BK][BM + 4];
    __shared__ float Bs[BK][BN + 4];

    int batch = blockIdx.z;
    A  += (long)batch * sA;
    Bm += (long)batch * sB;
    C  += (long)batch * sC;
    if (EPI == 3) C2 += (long)batch * sC;

    int bm = blockIdx.y * BM;
    int bn = blockIdx.x * BN;
    int tid = threadIdx.x;
    int tx = tid % (BN / TN);
    int ty = tid / (BN / TN);

    float acc[TM][TN];
#pragma unroll
    for (int i = 0; i < TM; i++)
#pragma unroll
        for (int j = 0; j < TN; j++) acc[i][j] = 0.f;

    for (int k0 = 0; k0 < K; k0 += BK) {
        // A tile: BM x BK, float4 along K
        constexpr int A_LOADS = BM * BK / (THREADS * 4);
#pragma unroll
        for (int i = 0; i < A_LOADS; i++) {
            int e  = tid + i * THREADS;
            int m  = e / (BK / 4);
            int kk = (e % (BK / 4)) * 4;
            float4 f = *reinterpret_cast<const float4*>(&A[(long)(bm + m) * lda + k0 + kk]);
            As[kk + 0][m] = f.x; As[kk + 1][m] = f.y;
            As[kk + 2][m] = f.z; As[kk + 3][m] = f.w;
        }
        // B tile
        constexpr int B_LOADS = BN * BK / (THREADS * 4);
        if (TB) {
#pragma unroll
            for (int i = 0; i < B_LOADS; i++) {
                int e  = tid + i * THREADS;
                int n  = e / (BK / 4);
                int kk = (e % (BK / 4)) * 4;
                float4 f = *reinterpret_cast<const float4*>(&Bm[(long)(bn + n) * ldb + k0 + kk]);
                Bs[kk + 0][n] = f.x; Bs[kk + 1][n] = f.y;
                Bs[kk + 2][n] = f.z; Bs[kk + 3][n] = f.w;
            }
        } else {
#pragma unroll
            for (int i = 0; i < B_LOADS; i++) {
                int e  = tid + i * THREADS;
                int kk = e / (BN / 4);
                int n  = (e % (BN / 4)) * 4;
                float4 f = *reinterpret_cast<const float4*>(&Bm[(long)(k0 + kk) * ldb + bn + n]);
                *reinterpret_cast<float4*>(&Bs[kk][n]) = f;
            }
        }
        __syncthreads();

#pragma unroll
        for (int kk = 0; kk < BK; kk++) {
            float ar[TM], br[TN];
#pragma unroll
            for (int i = 0; i < TM; i += 4) {
                float4 f = *reinterpret_cast<const float4*>(&As[kk][ty * TM + i]);
                ar[i] = f.x; ar[i + 1] = f.y; ar[i + 2] = f.z; ar[i + 3] = f.w;
            }
#pragma unroll
            for (int j = 0; j < TN; j += 4) {
                float4 f = *reinterpret_cast<const float4*>(&Bs[kk][tx * TN + j]);
                br[j] = f.x; br[j + 1] = f.y; br[j + 2] = f.z; br[j + 3] = f.w;
            }
#pragma unroll
            for (int i = 0; i < TM; i++)
#pragma unroll
                for (int j = 0; j < TN; j++) acc[i][j] += ar[i] * br[j];
        }
        __syncthreads();
    }

#pragma unroll
    for (int i = 0; i < TM; i++) {
        int row = bm + ty * TM + i;
#pragma unroll
        for (int j = 0; j < TN; j++) {
            int col = bn + tx * TN + j;
            long o = (long)row * ldc + col;
            float val = acc[i][j];
            if (EPI == 0)       C[o] = val;
            else if (EPI == 1)  C[o] = (row == col ? alpha : 0.f) - val;
            else if (EPI == 2)  C[o] = alpha * val;
            else if (EPI == 3) { C[o] = val; C2[o] = (row == col ? alpha : 0.f) - val; }
            else if (EPI == 5)  C[o] = val + bias[col] + resid[o];
        }
    }
}

template<int BM, int BN, int TM, int TN, bool TB, int EPI>
static void gemm(const float* A, const float* Bm, float* C, float* C2,
                 int M, int N, int K, int lda, int ldb, int ldc,
                 long sA, long sB, long sC, int batch, float alpha = 0.f,
                 const float* bias = nullptr, const float* resid = nullptr)
{
    dim3 g(N / BN, M / BM, batch);
    gemm_k<BM, BN, TM, TN, TB, EPI><<<g, 256>>>(A, Bm, C, C2, M, N, K, lda, ldb, ldc,
                                                sA, sB, sC, alpha, bias, resid);
}

// ---------------------------------------------------------------------------
// Scatter qkv [16384,1536] -> q,k,v as [B,H,N,D]; q scaled by DH^-0.5 = 1/8
// ---------------------------------------------------------------------------
__global__ void scatter_qkv_k(const float* __restrict__ qkv,
                              float* __restrict__ q, float* __restrict__ k,
                              float* __restrict__ v)
{
    int idx = blockIdx.x * 256 + threadIdx.x;   // ROWS * 1536
    int row = idx / (3 * DIM);
    int col = idx % (3 * DIM);
    float val = qkv[idx];
    int which = col / DIM;
    int c = col % DIM;
    int h = c / DHd, d = c % DHd;
    int b = row / Nseq, n = row % Nseq;
    size_t o = ((((size_t)b * NH + h) * Nseq) + n) * DHd + d;
    if (which == 0)      q[o] = val * 0.125f;
    else if (which == 1) k[o] = val;
    else                 v[o] = val;
}

// ---------------------------------------------------------------------------
// Landmarks: mean over LBL=16 consecutive tokens. grid BH*ML, block DHd
// ---------------------------------------------------------------------------
__global__ void landmark_k(const float* __restrict__ src, float* __restrict__ dst)
{
    int bm = blockIdx.x;        // bh*ML + m ; start row = bm*LBL
    int d = threadIdx.x;
    const float* p = src + (size_t)bm * LBL * DHd + d;
    float s = 0.f;
#pragma unroll
    for (int i = 0; i < LBL; i++) s += p[(size_t)i * DHd];
    dst[(size_t)bm * DHd + d] = s * (1.0f / LBL);
}

// ---------------------------------------------------------------------------
// Row softmax (in-place), one block (256 thr) per row, row staged in smem.
// ---------------------------------------------------------------------------
__global__ void softmax_k(float* __restrict__ p, int cols)
{
    extern __shared__ float sh[];
    __shared__ float red[256];
    float* row = p + (size_t)blockIdx.x * cols;
    int t = threadIdx.x;
    float m = -1e30f;
    for (int j = t; j < cols; j += 256) { float v = row[j]; sh[j] = v; m = fmaxf(m, v); }
    red[t] = m; __syncthreads();
    for (int o = 128; o > 0; o >>= 1) { if (t < o) red[t] = fmaxf(red[t], red[t + o]); __syncthreads(); }
    m = red[0];
    __syncthreads();
    float sum = 0.f;
    for (int j = t; j < cols; j += 256) { float e = __expf(sh[j] - m); sh[j] = e; sum += e; }
    red[t] = sum; __syncthreads();
    for (int o = 128; o > 0; o >>= 1) { if (t < o) red[t] += red[t + o]; __syncthreads(); }
    float inv = 1.0f / red[0];
    for (int j = t; j < cols; j += 256) row[j] = sh[j] * inv;
}

// ---------------------------------------------------------------------------
// Newton-Schulz pinv init. NOTE: jnp.max(col), jnp.max(row) are GLOBAL maxima
// over the whole [B,H,M] arrays (single scalar across all batches).
// ---------------------------------------------------------------------------
__global__ void pinv_absmax_k(const float* __restrict__ a2, float* __restrict__ red)
{
    int bh = blockIdx.x;
    const float* X = a2 + (size_t)bh * MM;
    int t = threadIdx.x;                 // 256
    float cs = 0.f, rs = 0.f;
    for (int j = 0; j < ML; j++) {
        cs += fabsf(X[(size_t)t * ML + j]);   // row t, sum over last axis
        rs += fabsf(X[(size_t)j * ML + t]);   // col t, sum over -2 axis
    }
    __shared__ float rc[256], rr[256];
    rc[t] = cs; rr[t] = rs; __syncthreads();
    for (int o = 128; o > 0; o >>= 1) {
        if (t < o) { rc[t] = fmaxf(rc[t], rc[t + o]); rr[t] = fmaxf(rr[t], rr[t + o]); }
        __syncthreads();
    }
    if (t == 0) { red[bh] = rc[0]; red[32 + bh] = rr[0]; }
}

__global__ void pinv_scalar_k(const float* __restrict__ red, float* __restrict__ scal)
{
    int t = threadIdx.x;   // 32
    float c = red[t], r = red[32 + t];
    for (int o = 16; o > 0; o >>= 1) {
        c = fmaxf(c, __shfl_down_sync(0xffffffffu, c, o));
        r = fmaxf(r, __shfl_down_sync(0xffffffffu, r, o));
    }
    if (t == 0) scal[0] = 1.0f / (c * r);
}

__global__ void pinv_zinit_k(const float* __restrict__ a2, const float* __restrict__ scal,
                             float* __restrict__ z)
{
    int idx = blockIdx.x * 256 + threadIdx.x;   // BH*MM
    int bh = idx >> 16;
    int r  = (idx >> 8) & 255;
    int c  = idx & 255;
    z[idx] = a2[((size_t)bh << 16) + ((size_t)c << 8) + r] * scal[0];
}

// ---------------------------------------------------------------------------
// Depthwise conv over sequence dim (K=33, pad 16), added into attn.
// ---------------------------------------------------------------------------
__global__ void conv_add_k(const float* __restrict__ v, const float* __restrict__ rw,
                           float* __restrict__ attn)
{
    int idx = blockIdx.x * 256 + threadIdx.x;   // BH*Nseq*DHd
    int d  = idx % DHd;
    int n  = (idx / DHd) % Nseq;
    int bh = idx / (DHd * Nseq);
    int h  = bh % NH;
    const float* vb = v + (size_t)bh * Nseq * DHd + d;
    float s = 0.f;
#pragma unroll
    for (int t = 0; t < KCONV; t++) {
        int nn = n + t - KCONV / 2;
        if (nn >= 0 && nn < Nseq) s += vb[(size_t)nn * DHd] * rw[h * KCONV + t];
    }
    attn[idx] += s;
}

// ---------------------------------------------------------------------------
// attn [B,H,N,D] -> [B*N, H*D]
// ---------------------------------------------------------------------------
__global__ void transpose_attn_k(const float* __restrict__ attn, float* __restrict__ o)
{
    int idx = blockIdx.x * 256 + threadIdx.x;   // ROWS*DIM
    int col = idx % DIM;
    int row = idx / DIM;
    int b = row / Nseq, n = row % Nseq;
    int h = col / DHd, d = col % DHd;
    o[idx] = attn[((((size_t)b * NH + h) * Nseq) + n) * DHd + d];
}

// ---------------------------------------------------------------------------
// Launch
// ---------------------------------------------------------------------------
extern "C" void kernel_launch(void* const* d_in, const int* in_sizes, int n_in,
                              void* d_out, int out_size)
{
    const float* x      = (const float*)d_in[0];
    const float* norm_w = (const float*)d_in[1];
    const float* norm_b = (const float*)d_in[2];
    const float* w_qkv  = (const float*)d_in[3];
    const float* w_out  = (const float*)d_in[4];
    const float* b_out  = (const float*)d_in[5];
    const float* res_w  = (const float*)d_in[6];
    float* out = (float*)d_out;

    float *xn, *qkv, *q, *k, *v, *ql, *kl, *a1, *a3, *a2;
    float *z0, *z1, *xz, *w1, *w2, *a3v, *zv, *attn, *attn_t, *red, *scal;
    cudaGetSymbolAddress((void**)&xn, g_xn);
    cudaGetSymbolAddress((void**)&qkv, g_qkv);
    cudaGetSymbolAddress((void**)&q, g_q);
    cudaGetSymbolAddress((void**)&k, g_k);
    cudaGetSymbolAddress((void**)&v, g_v);
    cudaGetSymbolAddress((void**)&ql, g_ql);
    cudaGetSymbolAddress((void**)&kl, g_kl);
    cudaGetSymbolAddress((void**)&a1, g_a1);
    cudaGetSymbolAddress((void**)&a3, g_a3);
    cudaGetSymbolAddress((void**)&a2, g_a2);
    cudaGetSymbolAddress((void**)&z0, g_z0);
    cudaGetSymbolAddress((void**)&z1, g_z1);
    cudaGetSymbolAddress((void**)&xz, g_xz);
    cudaGetSymbolAddress((void**)&w1, g_w1);
    cudaGetSymbolAddress((void**)&w2, g_w2);
    cudaGetSymbolAddress((void**)&a3v, g_a3v);
    cudaGetSymbolAddress((void**)&zv, g_zv);
    cudaGetSymbolAddress((void**)&attn, g_attn);
    cudaGetSymbolAddress((void**)&attn_t, g_attn_t);
    cudaGetSymbolAddress((void**)&red, g_red);
    cudaGetSymbolAddress((void**)&scal, g_scal);

    // 1. LayerNorm
    layernorm_k<<<ROWS, 128>>>(x, norm_w, norm_b, xn);

    // 2. QKV projection: [16384,512] x [512,1536]
    gemm<128, 128, 8, 8, false, 0>(xn, w_qkv, qkv, nullptr,
                                   ROWS, 3 * DIM, DIM, DIM, 3 * DIM, 3 * DIM,
                                   0, 0, 0, 1);
    scatter_qkv_k<<<ROWS * 3 * DIM / 256, 256>>>(qkv, q, k, v);

    // 3. Landmarks
    landmark_k<<<BH * ML, DHd>>>(q, ql);
    landmark_k<<<BH * ML, DHd>>>(k, kl);

    // 4. Similarities (NT: C = A * B^T over head dim)
    gemm<128, 128, 8, 8, true, 0>(q, kl, a1, nullptr,
                                  Nseq, ML, DHd, DHd, DHd, ML,
                                  (long)Nseq * DHd, (long)ML * DHd, (long)Nseq * ML, BH);
    gemm<64, 64, 4, 4, true, 0>(ql, kl, a2, nullptr,
                                ML, ML, DHd, DHd, DHd, ML,
                                (long)ML * DHd, (long)ML * DHd, (long)MM, BH);
    gemm<128, 128, 8, 8, true, 0>(ql, k, a3, nullptr,
                                  ML, Nseq, DHd, DHd, DHd, Nseq,
                                  (long)ML * DHd, (long)Nseq * DHd, (long)ML * Nseq, BH);

    // 5. Softmaxes
    softmax_k<<<BH * Nseq, 256, ML * 4>>>(a1, ML);
    softmax_k<<<BH * ML, 256, ML * 4>>>(a2, ML);
    softmax_k<<<BH * ML, 256, Nseq * 4>>>(a3, Nseq);

    // 6. pinv init (global max across all batches!)
    pinv_absmax_k<<<BH, 256>>>(a2, red);
    pinv_scalar_k<<<1, 32>>>(red, scal);
    pinv_zinit_k<<<BH * MM / 256, 256>>>(a2, scal, z0);

    // 7. Newton-Schulz iterations: z = 0.25 z (13I - xz(15I - xz(7I - xz)))
    float* zc = z0;
    float* zn = z1;
    for (int it = 0; it < 6; it++) {
        // xz = a2 @ z ; w1 = 7I - xz
        gemm<64, 64, 4, 4, false, 3>(a2, zc, xz, w1,
                                     ML, ML, ML, ML, ML, ML,
                                     (long)MM, (long)MM, (long)MM, BH, 7.f);
        // w2 = 15I - xz @ w1
        gemm<64, 64, 4, 4, false, 1>(xz, w1, w2, nullptr,
                                     ML, ML, ML, ML, ML, ML,
                                     (long)MM, (long)MM, (long)MM, BH, 15.f);
        // w1 = 13I - xz @ w2
        gemm<64, 64, 4, 4, false, 1>(xz, w2, w1, nullptr,
                                     ML, ML, ML, ML, ML, ML,
                                     (long)MM, (long)MM, (long)MM, BH, 13.f);
        // zn = 0.25 * zc @ w1
        gemm<64, 64, 4, 4, false, 2>(zc, w1, zn, nullptr,
                                     ML, ML, ML, ML, ML, ML,
                                     (long)MM, (long)MM, (long)MM, BH, 0.25f);
        float* tmp = zc; zc = zn; zn = tmp;
    }

    // 8. a3v = a3 @ v   [256,4096] x [4096,64]
    gemm<64, 64, 4, 4, false, 0>(a3, v, a3v, nullptr,
                                 ML, DHd, Nseq, Nseq, DHd, DHd,
                                 (long)ML * Nseq, (long)Nseq * DHd, (long)ML * DHd, BH);
    // 9. zv = z @ a3v   (reassociated: (a1 z)(a3 v) == a1 (z (a3 v)))
    gemm<64, 64, 4, 4, false, 0>(zc, a3v, zv, nullptr,
                                 ML, DHd, ML, ML, DHd, DHd,
                                 (long)MM, (long)ML * DHd, (long)ML * DHd, BH);
    // 10. attn = a1 @ zv  [4096,256] x [256,64]
    gemm<64, 64, 4, 4, false, 0>(a1, zv, attn, nullptr,
                                 Nseq, DHd, ML, ML, DHd, DHd,
                                 (long)Nseq * ML, (long)ML * DHd, (long)Nseq * DHd, BH);

    // 11. residual depthwise conv of v added into attn
    conv_add_k<<<BH * Nseq * DHd / 256, 256>>>(v, res_w, attn);

    // 12. transpose to [B*N, H*D]
    transpose_attn_k<<<ROWS * DIM / 256, 256>>>(attn, attn_t);

    // 13. out proj + bias + input residual -> d_out
    gemm<128, 128, 8, 8, false, 5>(attn_t, w_out, out, nullptr,
                                   ROWS, DIM, DIM, DIM, DIM, DIM,
                                   0, 0, 0, 1, 0.f, b_out, x);
}